// round 14
// baseline (speedup 1.0000x reference)
#include <cuda_runtime.h>
#include <cuda_fp16.h>
#include <math.h>

#define N_NODES 100000
#define N_EDGES 1600000
#define SCAN_NB ((N_NODES + 1023) / 1024)       // 98 blocks
#define GEMM_BLOCKS ((N_NODES + 127) / 128)     // 782
#define EDGE2_BLOCKS ((N_EDGES / 2 + 255) / 256) // 3125 (2 edges/thread)

// ---------------- scratch (device globals: no allocation allowed) ----------
__device__ __align__(16) __half g_h[N_NODES * 64];   // h' = dis*(in@W), fp16
__device__ __align__(16) __half g_agg[N_NODES * 64]; // relu(conv) fp16 (L1,L2)
__device__ float g_dis[N_NODES];               // rsqrt(deg+1)
__device__ int   g_cnt[N_NODES];               // in-degree; re-zeroed by scan
__device__ int   g_rowstart[N_NODES + 1];      // CSR row offsets
__device__ int   g_fill[N_NODES];              // atomic fill cursors
__device__ unsigned long long g_desc[SCAN_NB]; // lookback descriptors
__device__ __align__(16) int g_csr[N_EDGES];   // src only (h pre-scaled)

// ---------------- helpers ---------------------------------------------------
// per-block edge dtype sniff: JAX int64 LE with ids < 2^17 -> odd words all 0
__device__ __forceinline__ int detect_is64_block(const int* ei32, int* s64, int tid) {
    if (tid == 0) {
        int az = 1;
        #pragma unroll
        for (int j = 1; j < 128; j += 2) az &= (ei32[j] == 0);
        *s64 = az;
    }
    __syncthreads();
    return *s64;
}

__device__ __forceinline__ unsigned clampn(unsigned v) {
    return (v >= N_NODES) ? 0u : v;
}

// load edges 2t,2t+1 from array base (elements), dtype-aware
__device__ __forceinline__ int2 load_idx2(const int* ei32, long long base2t, int is64) {
    if (is64) {
        int4 v = *(const int4*)(ei32 + 2 * base2t);
        return make_int2((int)clampn((unsigned)v.x), (int)clampn((unsigned)v.z));
    } else {
        int2 v = *(const int2*)(ei32 + base2t);
        return make_int2((int)clampn((unsigned)v.x), (int)clampn((unsigned)v.y));
    }
}

__device__ __forceinline__ unsigned smem_u32(const void* p) {
    return (unsigned)__cvta_generic_to_shared(p);
}

// ---------------- tensor-core GEMM body: g_h = fp16( dis * (in @ W) ) -------
// 256 threads, 128 nodes/block; mma.sync m16n8k16, fp32 accumulate.
template <int NOUT, bool IN_EXT>
__device__ __forceinline__ void gemm_body(const float* __restrict__ ext_in,
                                          const float* __restrict__ W,
                                          int bidx, int tid) {
    constexpr int AS_STR = 72;            // halves; 144B = 9*16B row stride
    constexpr int WS_STR = (NOUT == 64) ? 72 : 40;
    constexpr int NT = NOUT / 8;
    __shared__ __align__(16) __half As[128 * AS_STR];
    __shared__ __align__(16) __half Ws[64 * WS_STR];

    const int base = bidx * 128;

    #pragma unroll 4
    for (int idx = tid; idx < 64 * NOUT / 2; idx += 256) {
        int row = idx / (NOUT / 2), c2 = idx % (NOUT / 2);
        float2 wv = ((const float2*)W)[idx];
        *(half2*)&Ws[row * WS_STR + c2 * 2] = __floats2half2_rn(wv.x, wv.y);
    }

    {
        int node = tid >> 1;
        int c0 = (tid & 1) * 32;
        int gnode = base + node;
        __half* dst = &As[node * AS_STR + c0];
        if (gnode < N_NODES) {
            if (IN_EXT) {
                const float4* src = (const float4*)(ext_in + (size_t)gnode * 64 + c0);
                #pragma unroll
                for (int i = 0; i < 8; i++) {
                    float4 v = src[i];
                    *(half2*)(dst + i * 4)     = __floats2half2_rn(v.x, v.y);
                    *(half2*)(dst + i * 4 + 2) = __floats2half2_rn(v.z, v.w);
                }
            } else {
                const uint4* src = (const uint4*)(g_agg + (size_t)gnode * 64 + c0);
                #pragma unroll
                for (int i = 0; i < 4; i++)
                    ((uint4*)dst)[i] = src[i];
            }
        } else {
            #pragma unroll
            for (int i = 0; i < 4; i++)
                ((uint4*)dst)[i] = make_uint4(0, 0, 0, 0);
        }
    }
    __syncthreads();

    const int warp = tid >> 5;
    const int lane = tid & 31;
    const int m0 = warp * 16;

    float acc[NT][4];
    #pragma unroll
    for (int n = 0; n < NT; n++)
        #pragma unroll
        for (int i = 0; i < 4; i++) acc[n][i] = 0.0f;

    const unsigned a_base = smem_u32(As);
    const unsigned w_base = smem_u32(Ws);

    #pragma unroll
    for (int ks = 0; ks < 4; ks++) {
        unsigned a0, a1, a2, a3;
        unsigned a_addr = a_base +
            (((m0 + (lane & 15)) * AS_STR + ks * 16 + ((lane >> 4) << 3)) << 1);
        asm volatile("ldmatrix.sync.aligned.m8n8.x4.shared.b16 {%0,%1,%2,%3}, [%4];"
                     : "=r"(a0), "=r"(a1), "=r"(a2), "=r"(a3) : "r"(a_addr));
        #pragma unroll
        for (int nt = 0; nt < NT; nt++) {
            unsigned b0, b1;
            unsigned b_addr = w_base +
                (((ks * 16 + (lane & 15)) * WS_STR + nt * 8) << 1);
            asm volatile("ldmatrix.sync.aligned.m8n8.x2.trans.shared.b16 {%0,%1}, [%2];"
                         : "=r"(b0), "=r"(b1) : "r"(b_addr));
            asm volatile(
                "mma.sync.aligned.m16n8k16.row.col.f32.f16.f16.f32 "
                "{%0,%1,%2,%3},{%4,%5,%6,%7},{%8,%9},{%0,%1,%2,%3};"
                : "+f"(acc[nt][0]), "+f"(acc[nt][1]), "+f"(acc[nt][2]), "+f"(acc[nt][3])
                : "r"(a0), "r"(a1), "r"(a2), "r"(a3), "r"(b0), "r"(b1));
        }
    }

    const int row = lane >> 2;
    const int cp  = (lane & 3) * 2;
    int node0 = base + m0 + row;
    int node1 = node0 + 8;
    float d0 = (node0 < N_NODES) ? g_dis[node0] : 0.f;
    float d1 = (node1 < N_NODES) ? g_dis[node1] : 0.f;
    #pragma unroll
    for (int nt = 0; nt < NT; nt++) {
        if (node0 < N_NODES)
            *(half2*)(g_h + (size_t)node0 * NOUT + nt * 8 + cp) =
                __floats2half2_rn(acc[nt][0] * d0, acc[nt][1] * d0);
        if (node1 < N_NODES)
            *(half2*)(g_h + (size_t)node1 * NOUT + nt * 8 + cp) =
                __floats2half2_rn(acc[nt][2] * d1, acc[nt][3] * d1);
    }
}

// ---------------- launch 0: hist, 2 edges/thread (+ desc reset) -------------
__global__ void __launch_bounds__(256)
hist_kernel(const int* __restrict__ ei32) {
    __shared__ int s64;
    int tid = threadIdx.x;
    if (blockIdx.x == 0 && tid < SCAN_NB) g_desc[tid] = 0ULL;
    int is64 = detect_is64_block(ei32, &s64, tid);
    int e2 = blockIdx.x * 256 + tid;
    if (e2 < N_EDGES / 2) {
        int2 d = load_idx2(ei32, (long long)N_EDGES + 2 * e2, is64);
        atomicAdd(&g_cnt[d.x], 1);
        atomicAdd(&g_cnt[d.y], 1);
    }
}

// ---------------- launch 1: single-pass scan (decoupled lookback) -----------
__global__ void __launch_bounds__(1024) scan_kernel() {
    __shared__ int s_warp[32];
    __shared__ int s_prefix;
    const unsigned FULL = 0xffffffffu;
    int tid = threadIdx.x, lane = tid & 31, wid = tid >> 5;
    int bid = blockIdx.x;
    int i = bid * 1024 + tid;
    int v = (i < N_NODES) ? g_cnt[i] : 0;

    int s = v;
    #pragma unroll
    for (int o = 1; o < 32; o <<= 1) {
        int t = __shfl_up_sync(FULL, s, o);
        if (lane >= o) s += t;
    }
    if (lane == 31) s_warp[wid] = s;
    __syncthreads();
    if (wid == 0) {
        int ws = s_warp[lane];
        #pragma unroll
        for (int o = 1; o < 32; o <<= 1) {
            int t = __shfl_up_sync(FULL, ws, o);
            if (lane >= o) ws += t;
        }
        s_warp[lane] = ws;
    }
    __syncthreads();
    int warp_excl = (wid == 0) ? 0 : s_warp[wid - 1];
    int incl  = s + warp_excl;
    int total = s_warp[31];

    if (wid == 0) {
        if (lane == 0) {
            unsigned long long d =
                ((unsigned long long)((bid == 0) ? 2 : 1) << 32) | (unsigned)total;
            atomicExch(&g_desc[bid], d);
        }
        int prefix = 0;
        if (bid > 0) {
            int j = bid - 1;
            while (j >= 0) {
                int idx = j - lane;
                bool valid = idx >= 0;
                unsigned long long d = 0;
                bool done;
                do {
                    if (valid) d = *((volatile unsigned long long*)&g_desc[idx]);
                    done = !valid || (d >> 32) != 0;
                } while (!__all_sync(FULL, done));
                unsigned pm = __ballot_sync(FULL, valid && (d >> 32) == 2);
                int contrib;
                if (pm) {
                    int fp = __ffs(pm) - 1;
                    contrib = (valid && lane <= fp) ? (int)(unsigned)d : 0;
                } else {
                    contrib = valid ? (int)(unsigned)d : 0;
                }
                #pragma unroll
                for (int o = 16; o > 0; o >>= 1)
                    contrib += __shfl_down_sync(FULL, contrib, o);
                if (lane == 0) prefix += contrib;
                if (pm) break;
                j -= 32;
            }
            if (lane == 0)
                atomicExch(&g_desc[bid], (2ULL << 32) | (unsigned)(prefix + total));
        }
        if (lane == 0) s_prefix = prefix;
    }
    __syncthreads();

    int pr = s_prefix;
    if (i < N_NODES) {
        int excl = pr + incl - v;
        g_rowstart[i] = excl;
        g_fill[i]     = excl;
        g_dis[i]      = rsqrtf((float)v + 1.0f);
        g_cnt[i]      = 0;                       // zero-on-entry invariant
    }
    if (bid == 0 && tid == 0) g_rowstart[N_NODES] = N_EDGES;
}

// ---------------- launch 2: fused gemm1 + CSR fill (2 edges/thread) ---------
__global__ void __launch_bounds__(256)
fused_gemm1_fill_kernel(const float* __restrict__ x, const float* __restrict__ W1,
                        const int* __restrict__ ei32) {
    __shared__ int s64;
    int tid = threadIdx.x;
    if (blockIdx.x < GEMM_BLOCKS) {
        gemm_body<64, true>(x, W1, blockIdx.x, tid);
    } else {
        int fb = blockIdx.x - GEMM_BLOCKS;
        int is64 = detect_is64_block(ei32, &s64, tid);
        int e2 = fb * 256 + tid;
        if (e2 < N_EDGES / 2) {
            int2 sn = load_idx2(ei32, (long long)2 * e2, is64);
            int2 dn = load_idx2(ei32, (long long)N_EDGES + 2 * e2, is64);
            int p0 = atomicAdd(&g_fill[dn.x], 1);
            g_csr[p0] = sn.x;
            int p1 = atomicAdd(&g_fill[dn.y], 1);
            g_csr[p1] = sn.y;
        }
    }
}

// ---------------- gather64: agg = fp16(relu(dis*(sum h' + h'self) + b)) ------
// 8-lane group PER NODE (4 nodes/warp); pairwise fp16 pre-add; unroll 4
// -> up to 8 row-loads in flight per group.
__global__ void __launch_bounds__(256, 5)
gather64_kernel(const float* __restrict__ b) {
    int node = (blockIdx.x * blockDim.x + threadIdx.x) >> 3;
    if (node >= N_NODES) return;
    int l8 = threadIdx.x & 7;

    float4 bv0 = ((const float4*)b)[l8 * 2];
    float4 bv1 = ((const float4*)b)[l8 * 2 + 1];

    int start = g_rowstart[node];
    int end   = g_rowstart[node + 1];

    float acc[8];
    #pragma unroll
    for (int t = 0; t < 8; t++) acc[t] = 0.0f;
    const uint4* hb = (const uint4*)g_h;

    int k = start;
    #pragma unroll 4
    for (; k + 1 < end; k += 2) {
        int s0 = g_csr[k];
        int s1 = g_csr[k + 1];
        uint4 v0 = hb[(unsigned)s0 * 8u + l8];
        uint4 v1 = hb[(unsigned)s1 * 8u + l8];
        const __half2* p0 = (const __half2*)&v0;
        const __half2* p1 = (const __half2*)&v1;
        #pragma unroll
        for (int u = 0; u < 4; u++) {
            float2 f = __half22float2(__hadd2(p0[u], p1[u]));
            acc[2 * u]     += f.x;
            acc[2 * u + 1] += f.y;
        }
    }
    if (k < end) {
        int s0 = g_csr[k];
        uint4 v0 = hb[(unsigned)s0 * 8u + l8];
        const __half2* p0 = (const __half2*)&v0;
        #pragma unroll
        for (int u = 0; u < 4; u++) {
            float2 f = __half22float2(p0[u]);
            acc[2 * u]     += f.x;
            acc[2 * u + 1] += f.y;
        }
    }

    float d = g_dis[node];
    uint4 sv = hb[(unsigned)node * 8u + l8];
    const __half2* sp = (const __half2*)&sv;
    const float* bp0 = (const float*)&bv0;
    const float* bp1 = (const float*)&bv1;
    uint4 pk;
    unsigned* pw = (unsigned*)&pk;
    #pragma unroll
    for (int u = 0; u < 4; u++) {
        float2 f = __half22float2(sp[u]);
        float bx = (u < 2) ? bp0[2 * u]     : bp1[2 * u - 4];
        float by = (u < 2) ? bp0[2 * u + 1] : bp1[2 * u - 3];
        float ox = fmaxf(fmaf(d, acc[2 * u]     + f.x, bx), 0.f);
        float oy = fmaxf(fmaf(d, acc[2 * u + 1] + f.y, by), 0.f);
        __half2 h2 = __floats2half2_rn(ox, oy);
        pw[u] = *(unsigned*)&h2;
    }
    ((uint4*)(g_agg + (size_t)node * 64))[l8] = pk;
}

// ---------------- gather32: 4-lane group per node, fp32 out, no relu ---------
__global__ void __launch_bounds__(256, 5)
gather32_kernel(const float* __restrict__ b, float* __restrict__ out) {
    int node = (blockIdx.x * blockDim.x + threadIdx.x) >> 2;
    if (node >= N_NODES) return;
    int l4 = threadIdx.x & 3;

    float4 bv0 = ((const float4*)b)[l4 * 2];
    float4 bv1 = ((const float4*)b)[l4 * 2 + 1];

    int start = g_rowstart[node];
    int end   = g_rowstart[node + 1];

    float acc[8];
    #pragma unroll
    for (int t = 0; t < 8; t++) acc[t] = 0.0f;
    const uint4* hb = (const uint4*)g_h;

    int k = start;
    #pragma unroll 4
    for (; k + 1 < end; k += 2) {
        int s0 = g_csr[k];
        int s1 = g_csr[k + 1];
        uint4 v0 = hb[(unsigned)s0 * 4u + l4];
        uint4 v1 = hb[(unsigned)s1 * 4u + l4];
        const __half2* p0 = (const __half2*)&v0;
        const __half2* p1 = (const __half2*)&v1;
        #pragma unroll
        for (int u = 0; u < 4; u++) {
            float2 f = __half22float2(__hadd2(p0[u], p1[u]));
            acc[2 * u]     += f.x;
            acc[2 * u + 1] += f.y;
        }
    }
    if (k < end) {
        int s0 = g_csr[k];
        uint4 v0 = hb[(unsigned)s0 * 4u + l4];
        const __half2* p0 = (const __half2*)&v0;
        #pragma unroll
        for (int u = 0; u < 4; u++) {
            float2 f = __half22float2(p0[u]);
            acc[2 * u]     += f.x;
            acc[2 * u + 1] += f.y;
        }
    }

    float d = g_dis[node];
    uint4 sv = hb[(unsigned)node * 4u + l4];
    const __half2* sp = (const __half2*)&sv;
    const float* bp0 = (const float*)&bv0;
    const float* bp1 = (const float*)&bv1;
    float o[8];
    #pragma unroll
    for (int u = 0; u < 4; u++) {
        float2 f = __half22float2(sp[u]);
        float bx = (u < 2) ? bp0[2 * u]     : bp1[2 * u - 4];
        float by = (u < 2) ? bp0[2 * u + 1] : bp1[2 * u - 3];
        o[2 * u]     = fmaf(d, acc[2 * u]     + f.x, bx);
        o[2 * u + 1] = fmaf(d, acc[2 * u + 1] + f.y, by);
    }
    float* ap = out + (size_t)node * 32 + l4 * 8;
    *(float4*)(ap)     = make_float4(o[0], o[1], o[2], o[3]);
    *(float4*)(ap + 4) = make_float4(o[4], o[5], o[6], o[7]);
}

// ---------------- plain GEMM kernels (layers 2,3) ---------------------------
template <int NOUT>
__global__ void __launch_bounds__(256)
gemm_kernel(const float* __restrict__ W) {
    gemm_body<NOUT, false>(nullptr, W, blockIdx.x, threadIdx.x);
}

// ---------------- launch -----------------------------------------------------
extern "C" void kernel_launch(void* const* d_in, const int* in_sizes, int n_in,
                              void* d_out, int out_size) {
    const float* x    = (const float*)d_in[0];
    const int*   ei32 = (const int*)d_in[1];   // int32 OR int64 (auto-detected)
    const float* W1 = (const float*)d_in[2];
    const float* b1 = (const float*)d_in[3];
    const float* W2 = (const float*)d_in[4];
    const float* b2 = (const float*)d_in[5];
    const float* W3 = (const float*)d_in[6];
    const float* b3 = (const float*)d_in[7];
    float* out = (float*)d_out;

    const int TPB = 256;
    const int g64_blocks = (N_NODES * 8 + TPB - 1) / TPB;   // 8 lanes/node
    const int g32_blocks = (N_NODES * 4 + TPB - 1) / TPB;   // 4 lanes/node

    // 0: degree hist (+ lookback-desc reset)
    hist_kernel<<<EDGE2_BLOCKS, TPB>>>(ei32);
    // 1: single-pass scan -> rowstart, dis, fill-init, cnt re-zero
    scan_kernel<<<SCAN_NB, 1024>>>();
    // 2: gemm1 (needs dis for pre-scaling) fused with CSR fill
    fused_gemm1_fill_kernel<<<GEMM_BLOCKS + EDGE2_BLOCKS, TPB>>>(x, W1, ei32);
    // 3: layer-1 gather (profiled slot)
    gather64_kernel<<<g64_blocks, TPB>>>(b1);
    // layer 2
    gemm_kernel<64><<<GEMM_BLOCKS, TPB>>>(W2);
    gather64_kernel<<<g64_blocks, TPB>>>(b2);
    // layer 3
    gemm_kernel<32><<<GEMM_BLOCKS, TPB>>>(W3);
    gather32_kernel<<<g32_blocks, TPB>>>(b3, out);
}

// round 15
// speedup vs baseline: 1.0672x; 1.0672x over previous
#include <cuda_runtime.h>
#include <cuda_fp16.h>
#include <math.h>

#define N_NODES 100000
#define N_EDGES 1600000
#define SCAN_NB ((N_NODES + 1023) / 1024)       // 98 blocks
#define GEMM_BLOCKS ((N_NODES + 127) / 128)     // 782
#define EDGE2_BLOCKS ((N_EDGES / 2 + 255) / 256) // 3125 (2 edges/thread)

// ---------------- scratch (device globals: no allocation allowed) ----------
__device__ __align__(16) __half g_h[N_NODES * 64];   // h' = dis*(in@W), fp16
__device__ __align__(16) __half g_agg[N_NODES * 64]; // relu(conv) fp16 (L1,L2)
__device__ float g_dis[N_NODES];               // rsqrt(deg+1)
__device__ int   g_cnt[N_NODES];               // in-degree; re-zeroed by scan
__device__ int   g_rowstart[N_NODES + 1];      // CSR row offsets
__device__ int   g_fill[N_NODES];              // atomic fill cursors
__device__ unsigned long long g_desc[SCAN_NB]; // lookback descriptors
__device__ __align__(16) int g_csr[N_EDGES];   // src only (h pre-scaled)

// ---------------- helpers ---------------------------------------------------
// per-block edge dtype sniff: JAX int64 LE with ids < 2^17 -> odd words all 0
__device__ __forceinline__ int detect_is64_block(const int* ei32, int* s64, int tid) {
    if (tid == 0) {
        int az = 1;
        #pragma unroll
        for (int j = 1; j < 128; j += 2) az &= (ei32[j] == 0);
        *s64 = az;
    }
    __syncthreads();
    return *s64;
}

__device__ __forceinline__ unsigned clampn(unsigned v) {
    return (v >= N_NODES) ? 0u : v;
}

// load edges 2t,2t+1 from array base (elements), dtype-aware
__device__ __forceinline__ int2 load_idx2(const int* ei32, long long base2t, int is64) {
    if (is64) {
        int4 v = *(const int4*)(ei32 + 2 * base2t);
        return make_int2((int)clampn((unsigned)v.x), (int)clampn((unsigned)v.z));
    } else {
        int2 v = *(const int2*)(ei32 + base2t);
        return make_int2((int)clampn((unsigned)v.x), (int)clampn((unsigned)v.y));
    }
}

__device__ __forceinline__ unsigned smem_u32(const void* p) {
    return (unsigned)__cvta_generic_to_shared(p);
}

// ---------------- tensor-core GEMM body: g_h = fp16( dis * (in @ W) ) -------
// 256 threads, 128 nodes/block; mma.sync m16n8k16, fp32 accumulate.
template <int NOUT, bool IN_EXT>
__device__ __forceinline__ void gemm_body(const float* __restrict__ ext_in,
                                          const float* __restrict__ W,
                                          int bidx, int tid) {
    constexpr int AS_STR = 72;            // halves; 144B = 9*16B row stride
    constexpr int WS_STR = (NOUT == 64) ? 72 : 40;
    constexpr int NT = NOUT / 8;
    __shared__ __align__(16) __half As[128 * AS_STR];
    __shared__ __align__(16) __half Ws[64 * WS_STR];

    const int base = bidx * 128;

    #pragma unroll 4
    for (int idx = tid; idx < 64 * NOUT / 2; idx += 256) {
        int row = idx / (NOUT / 2), c2 = idx % (NOUT / 2);
        float2 wv = ((const float2*)W)[idx];
        *(half2*)&Ws[row * WS_STR + c2 * 2] = __floats2half2_rn(wv.x, wv.y);
    }

    {
        int node = tid >> 1;
        int c0 = (tid & 1) * 32;
        int gnode = base + node;
        __half* dst = &As[node * AS_STR + c0];
        if (gnode < N_NODES) {
            if (IN_EXT) {
                const float4* src = (const float4*)(ext_in + (size_t)gnode * 64 + c0);
                #pragma unroll
                for (int i = 0; i < 8; i++) {
                    float4 v = src[i];
                    *(half2*)(dst + i * 4)     = __floats2half2_rn(v.x, v.y);
                    *(half2*)(dst + i * 4 + 2) = __floats2half2_rn(v.z, v.w);
                }
            } else {
                const uint4* src = (const uint4*)(g_agg + (size_t)gnode * 64 + c0);
                #pragma unroll
                for (int i = 0; i < 4; i++)
                    ((uint4*)dst)[i] = src[i];
            }
        } else {
            #pragma unroll
            for (int i = 0; i < 4; i++)
                ((uint4*)dst)[i] = make_uint4(0, 0, 0, 0);
        }
    }
    __syncthreads();

    const int warp = tid >> 5;
    const int lane = tid & 31;
    const int m0 = warp * 16;

    float acc[NT][4];
    #pragma unroll
    for (int n = 0; n < NT; n++)
        #pragma unroll
        for (int i = 0; i < 4; i++) acc[n][i] = 0.0f;

    const unsigned a_base = smem_u32(As);
    const unsigned w_base = smem_u32(Ws);

    #pragma unroll
    for (int ks = 0; ks < 4; ks++) {
        unsigned a0, a1, a2, a3;
        unsigned a_addr = a_base +
            (((m0 + (lane & 15)) * AS_STR + ks * 16 + ((lane >> 4) << 3)) << 1);
        asm volatile("ldmatrix.sync.aligned.m8n8.x4.shared.b16 {%0,%1,%2,%3}, [%4];"
                     : "=r"(a0), "=r"(a1), "=r"(a2), "=r"(a3) : "r"(a_addr));
        #pragma unroll
        for (int nt = 0; nt < NT; nt++) {
            unsigned b0, b1;
            unsigned b_addr = w_base +
                (((ks * 16 + (lane & 15)) * WS_STR + nt * 8) << 1);
            asm volatile("ldmatrix.sync.aligned.m8n8.x2.trans.shared.b16 {%0,%1}, [%2];"
                         : "=r"(b0), "=r"(b1) : "r"(b_addr));
            asm volatile(
                "mma.sync.aligned.m16n8k16.row.col.f32.f16.f16.f32 "
                "{%0,%1,%2,%3},{%4,%5,%6,%7},{%8,%9},{%0,%1,%2,%3};"
                : "+f"(acc[nt][0]), "+f"(acc[nt][1]), "+f"(acc[nt][2]), "+f"(acc[nt][3])
                : "r"(a0), "r"(a1), "r"(a2), "r"(a3), "r"(b0), "r"(b1));
        }
    }

    const int row = lane >> 2;
    const int cp  = (lane & 3) * 2;
    int node0 = base + m0 + row;
    int node1 = node0 + 8;
    float d0 = (node0 < N_NODES) ? g_dis[node0] : 0.f;
    float d1 = (node1 < N_NODES) ? g_dis[node1] : 0.f;
    #pragma unroll
    for (int nt = 0; nt < NT; nt++) {
        if (node0 < N_NODES)
            *(half2*)(g_h + (size_t)node0 * NOUT + nt * 8 + cp) =
                __floats2half2_rn(acc[nt][0] * d0, acc[nt][1] * d0);
        if (node1 < N_NODES)
            *(half2*)(g_h + (size_t)node1 * NOUT + nt * 8 + cp) =
                __floats2half2_rn(acc[nt][2] * d1, acc[nt][3] * d1);
    }
}

// ---------------- launch 0: hist, 2 edges/thread (+ desc reset) -------------
__global__ void __launch_bounds__(256)
hist_kernel(const int* __restrict__ ei32) {
    __shared__ int s64;
    int tid = threadIdx.x;
    if (blockIdx.x == 0 && tid < SCAN_NB) g_desc[tid] = 0ULL;
    int is64 = detect_is64_block(ei32, &s64, tid);
    int e2 = blockIdx.x * 256 + tid;
    if (e2 < N_EDGES / 2) {
        int2 d = load_idx2(ei32, (long long)N_EDGES + 2 * e2, is64);
        atomicAdd(&g_cnt[d.x], 1);
        atomicAdd(&g_cnt[d.y], 1);
    }
}

// ---------------- launch 1: single-pass scan (decoupled lookback) -----------
__global__ void __launch_bounds__(1024) scan_kernel() {
    __shared__ int s_warp[32];
    __shared__ int s_prefix;
    const unsigned FULL = 0xffffffffu;
    int tid = threadIdx.x, lane = tid & 31, wid = tid >> 5;
    int bid = blockIdx.x;
    int i = bid * 1024 + tid;
    int v = (i < N_NODES) ? g_cnt[i] : 0;

    int s = v;
    #pragma unroll
    for (int o = 1; o < 32; o <<= 1) {
        int t = __shfl_up_sync(FULL, s, o);
        if (lane >= o) s += t;
    }
    if (lane == 31) s_warp[wid] = s;
    __syncthreads();
    if (wid == 0) {
        int ws = s_warp[lane];
        #pragma unroll
        for (int o = 1; o < 32; o <<= 1) {
            int t = __shfl_up_sync(FULL, ws, o);
            if (lane >= o) ws += t;
        }
        s_warp[lane] = ws;
    }
    __syncthreads();
    int warp_excl = (wid == 0) ? 0 : s_warp[wid - 1];
    int incl  = s + warp_excl;
    int total = s_warp[31];

    if (wid == 0) {
        if (lane == 0) {
            unsigned long long d =
                ((unsigned long long)((bid == 0) ? 2 : 1) << 32) | (unsigned)total;
            atomicExch(&g_desc[bid], d);
        }
        int prefix = 0;
        if (bid > 0) {
            int j = bid - 1;
            while (j >= 0) {
                int idx = j - lane;
                bool valid = idx >= 0;
                unsigned long long d = 0;
                bool done;
                do {
                    if (valid) d = *((volatile unsigned long long*)&g_desc[idx]);
                    done = !valid || (d >> 32) != 0;
                } while (!__all_sync(FULL, done));
                unsigned pm = __ballot_sync(FULL, valid && (d >> 32) == 2);
                int contrib;
                if (pm) {
                    int fp = __ffs(pm) - 1;
                    contrib = (valid && lane <= fp) ? (int)(unsigned)d : 0;
                } else {
                    contrib = valid ? (int)(unsigned)d : 0;
                }
                #pragma unroll
                for (int o = 16; o > 0; o >>= 1)
                    contrib += __shfl_down_sync(FULL, contrib, o);
                if (lane == 0) prefix += contrib;
                if (pm) break;
                j -= 32;
            }
            if (lane == 0)
                atomicExch(&g_desc[bid], (2ULL << 32) | (unsigned)(prefix + total));
        }
        if (lane == 0) s_prefix = prefix;
    }
    __syncthreads();

    int pr = s_prefix;
    if (i < N_NODES) {
        int excl = pr + incl - v;
        g_rowstart[i] = excl;
        g_fill[i]     = excl;
        g_dis[i]      = rsqrtf((float)v + 1.0f);
        g_cnt[i]      = 0;                       // zero-on-entry invariant
    }
    if (bid == 0 && tid == 0) g_rowstart[N_NODES] = N_EDGES;
}

// ---------------- launch 2: fused gemm1 + CSR fill (2 edges/thread) ---------
__global__ void __launch_bounds__(256)
fused_gemm1_fill_kernel(const float* __restrict__ x, const float* __restrict__ W1,
                        const int* __restrict__ ei32) {
    __shared__ int s64;
    int tid = threadIdx.x;
    if (blockIdx.x < GEMM_BLOCKS) {
        gemm_body<64, true>(x, W1, blockIdx.x, tid);
    } else {
        int fb = blockIdx.x - GEMM_BLOCKS;
        int is64 = detect_is64_block(ei32, &s64, tid);
        int e2 = fb * 256 + tid;
        if (e2 < N_EDGES / 2) {
            int2 sn = load_idx2(ei32, (long long)2 * e2, is64);
            int2 dn = load_idx2(ei32, (long long)N_EDGES + 2 * e2, is64);
            int p0 = atomicAdd(&g_fill[dn.x], 1);
            g_csr[p0] = sn.x;
            int p1 = atomicAdd(&g_fill[dn.y], 1);
            g_csr[p1] = sn.y;
        }
    }
}

// ---------------- gather64: agg = fp16(relu(dis*(sum h' + h'self) + b)) ------
// 8-lane group PER NODE (4 nodes/warp); pairwise fp16 pre-add; unroll 2
// (R13 config: 40 regs, ~61% occ — unroll 4 regressed via occupancy).
__global__ void __launch_bounds__(256)
gather64_kernel(const float* __restrict__ b) {
    int node = (blockIdx.x * blockDim.x + threadIdx.x) >> 3;
    if (node >= N_NODES) return;
    int l8 = threadIdx.x & 7;

    float4 bv0 = ((const float4*)b)[l8 * 2];
    float4 bv1 = ((const float4*)b)[l8 * 2 + 1];

    int start = g_rowstart[node];
    int end   = g_rowstart[node + 1];

    float acc[8];
    #pragma unroll
    for (int t = 0; t < 8; t++) acc[t] = 0.0f;
    const uint4* hb = (const uint4*)g_h;

    int k = start;
    #pragma unroll 2
    for (; k + 1 < end; k += 2) {
        int s0 = g_csr[k];
        int s1 = g_csr[k + 1];
        uint4 v0 = hb[(unsigned)s0 * 8u + l8];
        uint4 v1 = hb[(unsigned)s1 * 8u + l8];
        const __half2* p0 = (const __half2*)&v0;
        const __half2* p1 = (const __half2*)&v1;
        #pragma unroll
        for (int u = 0; u < 4; u++) {
            float2 f = __half22float2(__hadd2(p0[u], p1[u]));
            acc[2 * u]     += f.x;
            acc[2 * u + 1] += f.y;
        }
    }
    if (k < end) {
        int s0 = g_csr[k];
        uint4 v0 = hb[(unsigned)s0 * 8u + l8];
        const __half2* p0 = (const __half2*)&v0;
        #pragma unroll
        for (int u = 0; u < 4; u++) {
            float2 f = __half22float2(p0[u]);
            acc[2 * u]     += f.x;
            acc[2 * u + 1] += f.y;
        }
    }

    float d = g_dis[node];
    uint4 sv = hb[(unsigned)node * 8u + l8];
    const __half2* sp = (const __half2*)&sv;
    const float* bp0 = (const float*)&bv0;
    const float* bp1 = (const float*)&bv1;
    uint4 pk;
    unsigned* pw = (unsigned*)&pk;
    #pragma unroll
    for (int u = 0; u < 4; u++) {
        float2 f = __half22float2(sp[u]);
        float bx = (u < 2) ? bp0[2 * u]     : bp1[2 * u - 4];
        float by = (u < 2) ? bp0[2 * u + 1] : bp1[2 * u - 3];
        float ox = fmaxf(fmaf(d, acc[2 * u]     + f.x, bx), 0.f);
        float oy = fmaxf(fmaf(d, acc[2 * u + 1] + f.y, by), 0.f);
        __half2 h2 = __floats2half2_rn(ox, oy);
        pw[u] = *(unsigned*)&h2;
    }
    ((uint4*)(g_agg + (size_t)node * 64))[l8] = pk;
}

// ---------------- gather32: 4-lane group per node, fp32 out, no relu ---------
__global__ void __launch_bounds__(256)
gather32_kernel(const float* __restrict__ b, float* __restrict__ out) {
    int node = (blockIdx.x * blockDim.x + threadIdx.x) >> 2;
    if (node >= N_NODES) return;
    int l4 = threadIdx.x & 3;

    float4 bv0 = ((const float4*)b)[l4 * 2];
    float4 bv1 = ((const float4*)b)[l4 * 2 + 1];

    int start = g_rowstart[node];
    int end   = g_rowstart[node + 1];

    float acc[8];
    #pragma unroll
    for (int t = 0; t < 8; t++) acc[t] = 0.0f;
    const uint4* hb = (const uint4*)g_h;

    int k = start;
    #pragma unroll 2
    for (; k + 1 < end; k += 2) {
        int s0 = g_csr[k];
        int s1 = g_csr[k + 1];
        uint4 v0 = hb[(unsigned)s0 * 4u + l4];
        uint4 v1 = hb[(unsigned)s1 * 4u + l4];
        const __half2* p0 = (const __half2*)&v0;
        const __half2* p1 = (const __half2*)&v1;
        #pragma unroll
        for (int u = 0; u < 4; u++) {
            float2 f = __half22float2(__hadd2(p0[u], p1[u]));
            acc[2 * u]     += f.x;
            acc[2 * u + 1] += f.y;
        }
    }
    if (k < end) {
        int s0 = g_csr[k];
        uint4 v0 = hb[(unsigned)s0 * 4u + l4];
        const __half2* p0 = (const __half2*)&v0;
        #pragma unroll
        for (int u = 0; u < 4; u++) {
            float2 f = __half22float2(p0[u]);
            acc[2 * u]     += f.x;
            acc[2 * u + 1] += f.y;
        }
    }

    float d = g_dis[node];
    uint4 sv = hb[(unsigned)node * 4u + l4];
    const __half2* sp = (const __half2*)&sv;
    const float* bp0 = (const float*)&bv0;
    const float* bp1 = (const float*)&bv1;
    float o[8];
    #pragma unroll
    for (int u = 0; u < 4; u++) {
        float2 f = __half22float2(sp[u]);
        float bx = (u < 2) ? bp0[2 * u]     : bp1[2 * u - 4];
        float by = (u < 2) ? bp0[2 * u + 1] : bp1[2 * u - 3];
        o[2 * u]     = fmaf(d, acc[2 * u]     + f.x, bx);
        o[2 * u + 1] = fmaf(d, acc[2 * u + 1] + f.y, by);
    }
    float* ap = out + (size_t)node * 32 + l4 * 8;
    *(float4*)(ap)     = make_float4(o[0], o[1], o[2], o[3]);
    *(float4*)(ap + 4) = make_float4(o[4], o[5], o[6], o[7]);
}

// ---------------- plain GEMM kernels (layers 2,3) ---------------------------
template <int NOUT>
__global__ void __launch_bounds__(256)
gemm_kernel(const float* __restrict__ W) {
    gemm_body<NOUT, false>(nullptr, W, blockIdx.x, threadIdx.x);
}

// ---------------- launch -----------------------------------------------------
extern "C" void kernel_launch(void* const* d_in, const int* in_sizes, int n_in,
                              void* d_out, int out_size) {
    const float* x    = (const float*)d_in[0];
    const int*   ei32 = (const int*)d_in[1];   // int32 OR int64 (auto-detected)
    const float* W1 = (const float*)d_in[2];
    const float* b1 = (const float*)d_in[3];
    const float* W2 = (const float*)d_in[4];
    const float* b2 = (const float*)d_in[5];
    const float* W3 = (const float*)d_in[6];
    const float* b3 = (const float*)d_in[7];
    float* out = (float*)d_out;

    const int TPB = 256;
    const int g64_blocks = (N_NODES * 8 + TPB - 1) / TPB;   // 8 lanes/node
    const int g32_blocks = (N_NODES * 4 + TPB - 1) / TPB;   // 4 lanes/node

    // 0: degree hist (+ lookback-desc reset)
    hist_kernel<<<EDGE2_BLOCKS, TPB>>>(ei32);
    // 1: single-pass scan -> rowstart, dis, fill-init, cnt re-zero
    scan_kernel<<<SCAN_NB, 1024>>>();
    // 2: gemm1 (needs dis for pre-scaling) fused with CSR fill
    fused_gemm1_fill_kernel<<<GEMM_BLOCKS + EDGE2_BLOCKS, TPB>>>(x, W1, ei32);
    // 3: layer-1 gather (profiled slot)
    gather64_kernel<<<g64_blocks, TPB>>>(b1);
    // layer 2
    gemm_kernel<64><<<GEMM_BLOCKS, TPB>>>(W2);
    gather64_kernel<<<g64_blocks, TPB>>>(b2);
    // layer 3
    gemm_kernel<32><<<GEMM_BLOCKS, TPB>>>(W3);
    gather32_kernel<<<g32_blocks, TPB>>>(b3, out);
}

// round 16
// speedup vs baseline: 1.0807x; 1.0127x over previous
#include <cuda_runtime.h>
#include <cuda_fp16.h>
#include <math.h>

#define N_NODES 100000
#define N_EDGES 1600000
#define SCAN_NB ((N_NODES + 1023) / 1024)       // 98 blocks
#define GEMM_BLOCKS ((N_NODES + 127) / 128)     // 782
#define EDGE2_BLOCKS ((N_EDGES / 2 + 255) / 256) // 3125 (2 edges/thread)

// ---------------- scratch (device globals: no allocation allowed) ----------
__device__ __align__(16) __half g_h[N_NODES * 64];   // h' = dis*(in@W), fp16
__device__ __align__(16) __half g_agg[N_NODES * 64]; // relu(conv) fp16 (L1,L2)
__device__ float g_dis[N_NODES];               // rsqrt(deg+1)
__device__ int   g_cnt[N_NODES];               // in-degree; re-zeroed by scan
__device__ int   g_rowstart[N_NODES + 1];      // CSR row offsets
__device__ int   g_fill[N_NODES];              // atomic fill cursors
__device__ unsigned long long g_desc[SCAN_NB]; // lookback descriptors
__device__ __align__(16) int g_csr[N_EDGES];   // src only (h pre-scaled)

// ---------------- helpers ---------------------------------------------------
// per-block edge dtype sniff: JAX int64 LE with ids < 2^17 -> odd words all 0
__device__ __forceinline__ int detect_is64_block(const int* ei32, int* s64, int tid) {
    if (tid == 0) {
        int az = 1;
        #pragma unroll
        for (int j = 1; j < 128; j += 2) az &= (ei32[j] == 0);
        *s64 = az;
    }
    __syncthreads();
    return *s64;
}

__device__ __forceinline__ unsigned clampn(unsigned v) {
    return (v >= N_NODES) ? 0u : v;
}

// load edges 2t,2t+1 from array base (elements), dtype-aware
__device__ __forceinline__ int2 load_idx2(const int* ei32, long long base2t, int is64) {
    if (is64) {
        int4 v = *(const int4*)(ei32 + 2 * base2t);
        return make_int2((int)clampn((unsigned)v.x), (int)clampn((unsigned)v.z));
    } else {
        int2 v = *(const int2*)(ei32 + base2t);
        return make_int2((int)clampn((unsigned)v.x), (int)clampn((unsigned)v.y));
    }
}

__device__ __forceinline__ unsigned smem_u32(const void* p) {
    return (unsigned)__cvta_generic_to_shared(p);
}

// ---------------- tensor-core GEMM body: g_h = fp16( dis * (in @ W) ) -------
// 256 threads, 128 nodes/block; mma.sync m16n8k16, fp32 accumulate.
template <int NOUT, bool IN_EXT>
__device__ __forceinline__ void gemm_body(const float* __restrict__ ext_in,
                                          const float* __restrict__ W,
                                          int bidx, int tid) {
    constexpr int AS_STR = 72;            // halves; 144B = 9*16B row stride
    constexpr int WS_STR = (NOUT == 64) ? 72 : 40;
    constexpr int NT = NOUT / 8;
    __shared__ __align__(16) __half As[128 * AS_STR];
    __shared__ __align__(16) __half Ws[64 * WS_STR];

    const int base = bidx * 128;

    #pragma unroll 4
    for (int idx = tid; idx < 64 * NOUT / 2; idx += 256) {
        int row = idx / (NOUT / 2), c2 = idx % (NOUT / 2);
        float2 wv = ((const float2*)W)[idx];
        *(half2*)&Ws[row * WS_STR + c2 * 2] = __floats2half2_rn(wv.x, wv.y);
    }

    {
        int node = tid >> 1;
        int c0 = (tid & 1) * 32;
        int gnode = base + node;
        __half* dst = &As[node * AS_STR + c0];
        if (gnode < N_NODES) {
            if (IN_EXT) {
                const float4* src = (const float4*)(ext_in + (size_t)gnode * 64 + c0);
                #pragma unroll
                for (int i = 0; i < 8; i++) {
                    float4 v = src[i];
                    *(half2*)(dst + i * 4)     = __floats2half2_rn(v.x, v.y);
                    *(half2*)(dst + i * 4 + 2) = __floats2half2_rn(v.z, v.w);
                }
            } else {
                const uint4* src = (const uint4*)(g_agg + (size_t)gnode * 64 + c0);
                #pragma unroll
                for (int i = 0; i < 4; i++)
                    ((uint4*)dst)[i] = src[i];
            }
        } else {
            #pragma unroll
            for (int i = 0; i < 4; i++)
                ((uint4*)dst)[i] = make_uint4(0, 0, 0, 0);
        }
    }
    __syncthreads();

    const int warp = tid >> 5;
    const int lane = tid & 31;
    const int m0 = warp * 16;

    float acc[NT][4];
    #pragma unroll
    for (int n = 0; n < NT; n++)
        #pragma unroll
        for (int i = 0; i < 4; i++) acc[n][i] = 0.0f;

    const unsigned a_base = smem_u32(As);
    const unsigned w_base = smem_u32(Ws);

    #pragma unroll
    for (int ks = 0; ks < 4; ks++) {
        unsigned a0, a1, a2, a3;
        unsigned a_addr = a_base +
            (((m0 + (lane & 15)) * AS_STR + ks * 16 + ((lane >> 4) << 3)) << 1);
        asm volatile("ldmatrix.sync.aligned.m8n8.x4.shared.b16 {%0,%1,%2,%3}, [%4];"
                     : "=r"(a0), "=r"(a1), "=r"(a2), "=r"(a3) : "r"(a_addr));
        #pragma unroll
        for (int nt = 0; nt < NT; nt++) {
            unsigned b0, b1;
            unsigned b_addr = w_base +
                (((ks * 16 + (lane & 15)) * WS_STR + nt * 8) << 1);
            asm volatile("ldmatrix.sync.aligned.m8n8.x2.trans.shared.b16 {%0,%1}, [%2];"
                         : "=r"(b0), "=r"(b1) : "r"(b_addr));
            asm volatile(
                "mma.sync.aligned.m16n8k16.row.col.f32.f16.f16.f32 "
                "{%0,%1,%2,%3},{%4,%5,%6,%7},{%8,%9},{%0,%1,%2,%3};"
                : "+f"(acc[nt][0]), "+f"(acc[nt][1]), "+f"(acc[nt][2]), "+f"(acc[nt][3])
                : "r"(a0), "r"(a1), "r"(a2), "r"(a3), "r"(b0), "r"(b1));
        }
    }

    const int row = lane >> 2;
    const int cp  = (lane & 3) * 2;
    int node0 = base + m0 + row;
    int node1 = node0 + 8;
    float d0 = (node0 < N_NODES) ? g_dis[node0] : 0.f;
    float d1 = (node1 < N_NODES) ? g_dis[node1] : 0.f;
    #pragma unroll
    for (int nt = 0; nt < NT; nt++) {
        if (node0 < N_NODES)
            *(half2*)(g_h + (size_t)node0 * NOUT + nt * 8 + cp) =
                __floats2half2_rn(acc[nt][0] * d0, acc[nt][1] * d0);
        if (node1 < N_NODES)
            *(half2*)(g_h + (size_t)node1 * NOUT + nt * 8 + cp) =
                __floats2half2_rn(acc[nt][2] * d1, acc[nt][3] * d1);
    }
}

// ---------------- launch 0: hist, 2 edges/thread (+ desc reset) -------------
__global__ void __launch_bounds__(256)
hist_kernel(const int* __restrict__ ei32) {
    __shared__ int s64;
    int tid = threadIdx.x;
    if (blockIdx.x == 0 && tid < SCAN_NB) g_desc[tid] = 0ULL;
    int is64 = detect_is64_block(ei32, &s64, tid);
    int e2 = blockIdx.x * 256 + tid;
    if (e2 < N_EDGES / 2) {
        int2 d = load_idx2(ei32, (long long)N_EDGES + 2 * e2, is64);
        atomicAdd(&g_cnt[d.x], 1);
        atomicAdd(&g_cnt[d.y], 1);
    }
}

// ---------------- launch 1: single-pass scan (decoupled lookback) -----------
__global__ void __launch_bounds__(1024) scan_kernel() {
    __shared__ int s_warp[32];
    __shared__ int s_prefix;
    const unsigned FULL = 0xffffffffu;
    int tid = threadIdx.x, lane = tid & 31, wid = tid >> 5;
    int bid = blockIdx.x;
    int i = bid * 1024 + tid;
    int v = (i < N_NODES) ? g_cnt[i] : 0;

    int s = v;
    #pragma unroll
    for (int o = 1; o < 32; o <<= 1) {
        int t = __shfl_up_sync(FULL, s, o);
        if (lane >= o) s += t;
    }
    if (lane == 31) s_warp[wid] = s;
    __syncthreads();
    if (wid == 0) {
        int ws = s_warp[lane];
        #pragma unroll
        for (int o = 1; o < 32; o <<= 1) {
            int t = __shfl_up_sync(FULL, ws, o);
            if (lane >= o) ws += t;
        }
        s_warp[lane] = ws;
    }
    __syncthreads();
    int warp_excl = (wid == 0) ? 0 : s_warp[wid - 1];
    int incl  = s + warp_excl;
    int total = s_warp[31];

    if (wid == 0) {
        if (lane == 0) {
            unsigned long long d =
                ((unsigned long long)((bid == 0) ? 2 : 1) << 32) | (unsigned)total;
            atomicExch(&g_desc[bid], d);
        }
        int prefix = 0;
        if (bid > 0) {
            int j = bid - 1;
            while (j >= 0) {
                int idx = j - lane;
                bool valid = idx >= 0;
                unsigned long long d = 0;
                bool done;
                do {
                    if (valid) d = *((volatile unsigned long long*)&g_desc[idx]);
                    done = !valid || (d >> 32) != 0;
                } while (!__all_sync(FULL, done));
                unsigned pm = __ballot_sync(FULL, valid && (d >> 32) == 2);
                int contrib;
                if (pm) {
                    int fp = __ffs(pm) - 1;
                    contrib = (valid && lane <= fp) ? (int)(unsigned)d : 0;
                } else {
                    contrib = valid ? (int)(unsigned)d : 0;
                }
                #pragma unroll
                for (int o = 16; o > 0; o >>= 1)
                    contrib += __shfl_down_sync(FULL, contrib, o);
                if (lane == 0) prefix += contrib;
                if (pm) break;
                j -= 32;
            }
            if (lane == 0)
                atomicExch(&g_desc[bid], (2ULL << 32) | (unsigned)(prefix + total));
        }
        if (lane == 0) s_prefix = prefix;
    }
    __syncthreads();

    int pr = s_prefix;
    if (i < N_NODES) {
        int excl = pr + incl - v;
        g_rowstart[i] = excl;
        g_fill[i]     = excl;
        g_dis[i]      = rsqrtf((float)v + 1.0f);
        g_cnt[i]      = 0;                       // zero-on-entry invariant
    }
    if (bid == 0 && tid == 0) g_rowstart[N_NODES] = N_EDGES;
}

// ---------------- launch 2: fused gemm1 + CSR fill (2 edges/thread) ---------
__global__ void __launch_bounds__(256)
fused_gemm1_fill_kernel(const float* __restrict__ x, const float* __restrict__ W1,
                        const int* __restrict__ ei32) {
    __shared__ int s64;
    int tid = threadIdx.x;
    if (blockIdx.x < GEMM_BLOCKS) {
        gemm_body<64, true>(x, W1, blockIdx.x, tid);
    } else {
        int fb = blockIdx.x - GEMM_BLOCKS;
        int is64 = detect_is64_block(ei32, &s64, tid);
        int e2 = fb * 256 + tid;
        if (e2 < N_EDGES / 2) {
            int2 sn = load_idx2(ei32, (long long)2 * e2, is64);
            int2 dn = load_idx2(ei32, (long long)N_EDGES + 2 * e2, is64);
            int p0 = atomicAdd(&g_fill[dn.x], 1);
            g_csr[p0] = sn.x;
            int p1 = atomicAdd(&g_fill[dn.y], 1);
            g_csr[p1] = sn.y;
        }
    }
}

// ---------------- gather64: agg = fp16(relu(dis*(sum h' + h'self) + b)) ------
// 8-lane group PER NODE (4 nodes/warp); pairwise fp16 pre-add; unroll 2.
// __launch_bounds__(256,8) forces <=32 regs -> 64 warps/SM (occupancy play;
// bias loaded in epilogue, not held across the loop).
__global__ void __launch_bounds__(256, 8)
gather64_kernel(const float* __restrict__ b) {
    int node = (blockIdx.x * blockDim.x + threadIdx.x) >> 3;
    if (node >= N_NODES) return;
    int l8 = threadIdx.x & 7;

    int start = g_rowstart[node];
    int end   = g_rowstart[node + 1];

    float acc[8];
    #pragma unroll
    for (int t = 0; t < 8; t++) acc[t] = 0.0f;
    const uint4* hb = (const uint4*)g_h;

    int k = start;
    #pragma unroll 2
    for (; k + 1 < end; k += 2) {
        int s0 = g_csr[k];
        int s1 = g_csr[k + 1];
        uint4 v0 = hb[(unsigned)s0 * 8u + l8];
        uint4 v1 = hb[(unsigned)s1 * 8u + l8];
        const __half2* p0 = (const __half2*)&v0;
        const __half2* p1 = (const __half2*)&v1;
        #pragma unroll
        for (int u = 0; u < 4; u++) {
            float2 f = __half22float2(__hadd2(p0[u], p1[u]));
            acc[2 * u]     += f.x;
            acc[2 * u + 1] += f.y;
        }
    }
    if (k < end) {
        int s0 = g_csr[k];
        uint4 v0 = hb[(unsigned)s0 * 8u + l8];
        const __half2* p0 = (const __half2*)&v0;
        #pragma unroll
        for (int u = 0; u < 4; u++) {
            float2 f = __half22float2(p0[u]);
            acc[2 * u]     += f.x;
            acc[2 * u + 1] += f.y;
        }
    }

    // epilogue: self-loop + scale + bias (loaded here; L1-resident) + relu
    float d = g_dis[node];
    uint4 sv = hb[(unsigned)node * 8u + l8];
    const __half2* sp = (const __half2*)&sv;
    float4 bv0 = ((const float4*)b)[l8 * 2];
    float4 bv1 = ((const float4*)b)[l8 * 2 + 1];
    const float* bp0 = (const float*)&bv0;
    const float* bp1 = (const float*)&bv1;
    uint4 pk;
    unsigned* pw = (unsigned*)&pk;
    #pragma unroll
    for (int u = 0; u < 4; u++) {
        float2 f = __half22float2(sp[u]);
        float bx = (u < 2) ? bp0[2 * u]     : bp1[2 * u - 4];
        float by = (u < 2) ? bp0[2 * u + 1] : bp1[2 * u - 3];
        float ox = fmaxf(fmaf(d, acc[2 * u]     + f.x, bx), 0.f);
        float oy = fmaxf(fmaf(d, acc[2 * u + 1] + f.y, by), 0.f);
        __half2 h2 = __floats2half2_rn(ox, oy);
        pw[u] = *(unsigned*)&h2;
    }
    ((uint4*)(g_agg + (size_t)node * 64))[l8] = pk;
}

// ---------------- gather32: 4-lane group per node, fp32 out, no relu ---------
__global__ void __launch_bounds__(256, 8)
gather32_kernel(const float* __restrict__ b, float* __restrict__ out) {
    int node = (blockIdx.x * blockDim.x + threadIdx.x) >> 2;
    if (node >= N_NODES) return;
    int l4 = threadIdx.x & 3;

    int start = g_rowstart[node];
    int end   = g_rowstart[node + 1];

    float acc[8];
    #pragma unroll
    for (int t = 0; t < 8; t++) acc[t] = 0.0f;
    const uint4* hb = (const uint4*)g_h;

    int k = start;
    #pragma unroll 2
    for (; k + 1 < end; k += 2) {
        int s0 = g_csr[k];
        int s1 = g_csr[k + 1];
        uint4 v0 = hb[(unsigned)s0 * 4u + l4];
        uint4 v1 = hb[(unsigned)s1 * 4u + l4];
        const __half2* p0 = (const __half2*)&v0;
        const __half2* p1 = (const __half2*)&v1;
        #pragma unroll
        for (int u = 0; u < 4; u++) {
            float2 f = __half22float2(__hadd2(p0[u], p1[u]));
            acc[2 * u]     += f.x;
            acc[2 * u + 1] += f.y;
        }
    }
    if (k < end) {
        int s0 = g_csr[k];
        uint4 v0 = hb[(unsigned)s0 * 4u + l4];
        const __half2* p0 = (const __half2*)&v0;
        #pragma unroll
        for (int u = 0; u < 4; u++) {
            float2 f = __half22float2(p0[u]);
            acc[2 * u]     += f.x;
            acc[2 * u + 1] += f.y;
        }
    }

    float d = g_dis[node];
    uint4 sv = hb[(unsigned)node * 4u + l4];
    const __half2* sp = (const __half2*)&sv;
    float4 bv0 = ((const float4*)b)[l4 * 2];
    float4 bv1 = ((const float4*)b)[l4 * 2 + 1];
    const float* bp0 = (const float*)&bv0;
    const float* bp1 = (const float*)&bv1;
    float o[8];
    #pragma unroll
    for (int u = 0; u < 4; u++) {
        float2 f = __half22float2(sp[u]);
        float bx = (u < 2) ? bp0[2 * u]     : bp1[2 * u - 4];
        float by = (u < 2) ? bp0[2 * u + 1] : bp1[2 * u - 3];
        o[2 * u]     = fmaf(d, acc[2 * u]     + f.x, bx);
        o[2 * u + 1] = fmaf(d, acc[2 * u + 1] + f.y, by);
    }
    float* ap = out + (size_t)node * 32 + l4 * 8;
    *(float4*)(ap)     = make_float4(o[0], o[1], o[2], o[3]);
    *(float4*)(ap + 4) = make_float4(o[4], o[5], o[6], o[7]);
}

// ---------------- plain GEMM kernels (layers 2,3) ---------------------------
template <int NOUT>
__global__ void __launch_bounds__(256)
gemm_kernel(const float* __restrict__ W) {
    gemm_body<NOUT, false>(nullptr, W, blockIdx.x, threadIdx.x);
}

// ---------------- launch -----------------------------------------------------
extern "C" void kernel_launch(void* const* d_in, const int* in_sizes, int n_in,
                              void* d_out, int out_size) {
    const float* x    = (const float*)d_in[0];
    const int*   ei32 = (const int*)d_in[1];   // int32 OR int64 (auto-detected)
    const float* W1 = (const float*)d_in[2];
    const float* b1 = (const float*)d_in[3];
    const float* W2 = (const float*)d_in[4];
    const float* b2 = (const float*)d_in[5];
    const float* W3 = (const float*)d_in[6];
    const float* b3 = (const float*)d_in[7];
    float* out = (float*)d_out;

    const int TPB = 256;
    const int g64_blocks = (N_NODES * 8 + TPB - 1) / TPB;   // 8 lanes/node
    const int g32_blocks = (N_NODES * 4 + TPB - 1) / TPB;   // 4 lanes/node

    // 0: degree hist (+ lookback-desc reset)
    hist_kernel<<<EDGE2_BLOCKS, TPB>>>(ei32);
    // 1: single-pass scan -> rowstart, dis, fill-init, cnt re-zero
    scan_kernel<<<SCAN_NB, 1024>>>();
    // 2: gemm1 (needs dis for pre-scaling) fused with CSR fill
    fused_gemm1_fill_kernel<<<GEMM_BLOCKS + EDGE2_BLOCKS, TPB>>>(x, W1, ei32);
    // 3: layer-1 gather (profiled slot)
    gather64_kernel<<<g64_blocks, TPB>>>(b1);
    // layer 2
    gemm_kernel<64><<<GEMM_BLOCKS, TPB>>>(W2);
    gather64_kernel<<<g64_blocks, TPB>>>(b2);
    // layer 3
    gemm_kernel<32><<<GEMM_BLOCKS, TPB>>>(W3);
    gather32_kernel<<<g32_blocks, TPB>>>(b3, out);
}